// round 16
// baseline (speedup 1.0000x reference)
#include <cuda_runtime.h>
#include <cuda_fp16.h>
#include <cstdint>
#include <math.h>

#define D_MODEL 1024
#define N_HEADS 16
#define HEAD_DIM 64
#define BATCH 2
#define SEQ 2048

// ---------------------------------------------------------------------------
// Scratch (allocation-free rule: __device__ globals)
// ---------------------------------------------------------------------------
__device__ __half g_xh[4096 * 1024];         // x fp16
__device__ __half g_w1h[3072 * 1024];        // Wqkv^T fp16  [N,K]
__device__ __half g_w2h[1024 * 1024];        // Wout^T fp16  [N,K]
// q/k/v single fp16, [B,H,T,64] (q prescaled by 0.125)
__device__ __half g_qh[BATCH * N_HEADS * SEQ * 64];
__device__ __half g_kh[BATCH * N_HEADS * SEQ * 64];
__device__ __half g_vh[BATCH * N_HEADS * SEQ * 64];
// attention output (ctx) single fp16, [m=T*B rows][1024]
__device__ __half g_chi[4096 * 1024];

// ---------------------------------------------------------------------------
// PTX helpers (plain sm_103-compatible: mma.sync / ldmatrix / cp.async)
// ---------------------------------------------------------------------------
__device__ __forceinline__ uint32_t smem_to_u32(const void* p) {
    uint32_t a;
    asm("{ .reg .u64 t; cvta.to.shared.u64 t, %1; cvt.u32.u64 %0, t; }" : "=r"(a) : "l"(p));
    return a;
}
__device__ __forceinline__ void cp_async16(uint32_t dst, const void* src) {
    asm volatile("cp.async.cg.shared.global [%0], [%1], 16;" :: "r"(dst), "l"(src) : "memory");
}
#define CP_COMMIT() asm volatile("cp.async.commit_group;" ::: "memory")
#define CP_WAIT(n)  asm volatile("cp.async.wait_group %0;" :: "n"(n) : "memory")

__device__ __forceinline__ void ldsm_x4(uint32_t& r0, uint32_t& r1, uint32_t& r2, uint32_t& r3,
                                        uint32_t addr) {
    asm volatile("ldmatrix.sync.aligned.m8n8.x4.shared.b16 {%0,%1,%2,%3}, [%4];"
                 : "=r"(r0), "=r"(r1), "=r"(r2), "=r"(r3) : "r"(addr));
}
__device__ __forceinline__ void ldsm_x4_t(uint32_t& r0, uint32_t& r1, uint32_t& r2, uint32_t& r3,
                                          uint32_t addr) {
    asm volatile("ldmatrix.sync.aligned.m8n8.x4.trans.shared.b16 {%0,%1,%2,%3}, [%4];"
                 : "=r"(r0), "=r"(r1), "=r"(r2), "=r"(r3) : "r"(addr));
}
__device__ __forceinline__ void mma_f16(float c[4], const uint32_t a[4], const uint32_t b[2]) {
    asm volatile(
        "mma.sync.aligned.m16n8k16.row.col.f32.f16.f16.f32 "
        "{%0,%1,%2,%3}, {%4,%5,%6,%7}, {%8,%9}, {%0,%1,%2,%3};"
        : "+f"(c[0]), "+f"(c[1]), "+f"(c[2]), "+f"(c[3])
        : "r"(a[0]), "r"(a[1]), "r"(a[2]), "r"(a[3]), "r"(b[0]), "r"(b[1]));
}

__device__ __forceinline__ uint32_t pack2h(float x, float y) {
    __half2 h2 = __halves2half2(__float2half(x), __float2half(y));
    return *(uint32_t*)&h2;
}
// exp2 of a pair, result as packed fp16x2 (input pre-scaled by log2e)
__device__ __forceinline__ uint32_t exp2h2(float x, float y) {
    __half2 h = __floats2half2_rn(x, y);
    uint32_t r = *(uint32_t*)&h;
    uint32_t d;
    asm("ex2.approx.f16x2 %0, %1;" : "=r"(d) : "r"(r));
    return d;
}

// ---------------------------------------------------------------------------
// Conversion kernels
// ---------------------------------------------------------------------------
__global__ __launch_bounds__(256) void convert_lin(
    const float* __restrict__ in, __half* __restrict__ out, int n4)
{
    int i = blockIdx.x * blockDim.x + threadIdx.x;
    if (i >= n4) return;
    float4 v = ((const float4*)in)[i];
    ((__half2*)out)[i * 2]     = __floats2half2_rn(v.x, v.y);
    ((__half2*)out)[i * 2 + 1] = __floats2half2_rn(v.z, v.w);
}

// W[K,N] fp32 -> Wt [N,K] fp16 (transpose, round-to-nearest). 32x32 tiles.
__global__ __launch_bounds__(256) void convert_T(
    const float* __restrict__ W, __half* __restrict__ hi, int K, int N)
{
    __shared__ float t[32][33];
    const int n0 = blockIdx.x * 32;
    const int k0 = blockIdx.y * 32;
#pragma unroll
    for (int i = 0; i < 4; i++) {
        int k = k0 + threadIdx.y + i * 8;
        t[threadIdx.y + i * 8][threadIdx.x] = W[(size_t)k * N + n0 + threadIdx.x];
    }
    __syncthreads();
#pragma unroll
    for (int i = 0; i < 4; i++) {
        int nn = n0 + threadIdx.y + i * 8;
        hi[(size_t)nn * K + k0 + threadIdx.x] = __float2half(t[threadIdx.x][threadIdx.y + i * 8]);
    }
}

// ---------------------------------------------------------------------------
// fp16 GEMM (single MMA): C = Ah[M,K=1024] @ Bh[N,K]^T + bias
// CTA tile 128(M) x 128(N), BK=32, 256 threads (8 warps: 4M x 2N),
// warp tile 32x64. 4-stage cp.async ring, CP_WAIT(2), one barrier per kt,
// 2 CTAs/SM (81.9 KB smem).
// MODE 1: QKV epilogue -> q/k/v fp16 [B,H,T,64] (q scaled by 0.125).
// MODE 2: fp32 C + bias.
// ---------------------------------------------------------------------------
#define BK 32
#define ASTRIDE 40                        // fp16 elems per smem row (32 + 8 pad)
#define TILE_BYTES (128 * ASTRIDE * 2)    // 10240
#define T_AH 0
#define T_BH  TILE_BYTES
#define STAGE_BYTES (2 * TILE_BYTES)      // 20480
#define GSMEM_TOTAL (4 * STAGE_BYTES)     // 81920

template <int MODE>
__global__ __launch_bounds__(256, 2) void gemm_mma(
    const __half* __restrict__ Ah, const __half* __restrict__ Bh,
    const float* __restrict__ bias, float* __restrict__ C,
    __half* __restrict__ qh, __half* __restrict__ kh, __half* __restrict__ vh,
    int M, int N, int K)
{
    extern __shared__ char smem[];
    const uint32_t smem_base = smem_to_u32(smem);
    const int tid  = threadIdx.x;
    const int wid  = tid >> 5;
    const int lane = tid & 31;
    const int bm = blockIdx.y * 128;
    const int bn = blockIdx.x * 128;
    const int wm = (wid & 3) * 32;
    const int wn = (wid >> 2) * 64;

    auto load_stage = [&](int it) {
        const uint32_t sb = smem_base + (it & 3) * STAGE_BYTES;
        const int k0 = it * BK;
#pragma unroll
        for (int c = tid; c < 1024; c += 256) {
            int kc = (c & 3) * 8;
            const __half* src;
            uint32_t dst;
            if (c < 512) {             // A
                int r = c >> 2;
                src = Ah + (size_t)(bm + r) * K + k0 + kc;
                dst = sb + T_AH + (r * ASTRIDE + kc) * 2;
            } else {                   // B
                int r = (c - 512) >> 2;
                src = Bh + (size_t)(bn + r) * K + k0 + kc;
                dst = sb + T_BH + (r * ASTRIDE + kc) * 2;
            }
            cp_async16(dst, src);
        }
    };

    const int NK = K / BK;
    load_stage(0); CP_COMMIT();
    load_stage(1); CP_COMMIT();
    load_stage(2); CP_COMMIT();

    float acc[2][8][4];
#pragma unroll
    for (int mt = 0; mt < 2; mt++)
#pragma unroll
        for (int nt = 0; nt < 8; nt++)
#pragma unroll
            for (int i = 0; i < 4; i++) acc[mt][nt][i] = 0.f;

    const int lrow = lane & 15;
    const int lcol = (lane >> 4) * 8;

    for (int kt = 0; kt < NK; kt++) {
        CP_WAIT(2);
        __syncthreads();       // single barrier per kt (4-stage ring)
        if (kt + 3 < NK) load_stage(kt + 3);
        CP_COMMIT();           // unconditional (possibly empty group)
        const uint32_t sb = smem_base + (kt & 3) * STAGE_BYTES;

#pragma unroll
        for (int ks = 0; ks < 2; ks++) {
            uint32_t ah[2][4];
#pragma unroll
            for (int mt = 0; mt < 2; mt++) {
                uint32_t off = ((wm + mt * 16 + lrow) * ASTRIDE + ks * 16 + lcol) * 2;
                ldsm_x4(ah[mt][0], ah[mt][1], ah[mt][2], ah[mt][3], sb + T_AH + off);
            }
            uint32_t bh[8][2];
#pragma unroll
            for (int np = 0; np < 4; np++) {
                uint32_t off = ((wn + np * 16 + lrow) * ASTRIDE + ks * 16 + lcol) * 2;
                uint32_t r0, r1, r2, r3;
                ldsm_x4(r0, r1, r2, r3, sb + T_BH + off);
                bh[np * 2][0] = r0; bh[np * 2][1] = r2;
                bh[np * 2 + 1][0] = r1; bh[np * 2 + 1][1] = r3;
            }
#pragma unroll
            for (int mt = 0; mt < 2; mt++)
#pragma unroll
                for (int nt = 0; nt < 8; nt++)
                    mma_f16(acc[mt][nt], ah[mt], bh[nt]);
        }
    }

    const int trow = lane >> 2;
    const int tcol = (lane & 3) * 2;

    if (MODE == 2) {
#pragma unroll
        for (int mt = 0; mt < 2; mt++) {
            const int grow = bm + wm + mt * 16 + trow;
#pragma unroll
            for (int nt = 0; nt < 8; nt++) {
                const int gcol = bn + wn + nt * 8 + tcol;
                float b0 = bias[gcol], b1 = bias[gcol + 1];
                float2 o0 = {acc[mt][nt][0] + b0, acc[mt][nt][1] + b1};
                float2 o1 = {acc[mt][nt][2] + b0, acc[mt][nt][3] + b1};
                *(float2*)(C + (size_t)grow * N + gcol)       = o0;
                *(float2*)(C + (size_t)(grow + 8) * N + gcol) = o1;
            }
        }
    } else {
        const int sec = bn >> 10;   // 0:q 1:k 2:v (uniform per CTA: 1024%128==0)
        __half* dhi = (sec == 0) ? qh : (sec == 1) ? kh : vh;
        const float scl = (sec == 0) ? 0.125f : 1.f;
#pragma unroll
        for (int mt = 0; mt < 2; mt++) {
            const int grow = bm + wm + mt * 16 + trow;
#pragma unroll
            for (int nt = 0; nt < 8; nt++) {
                const int gcol = bn + wn + nt * 8 + tcol;
                const int hh = (gcol >> 6) & 15;
                const int dd = gcol & 63;
                float b0 = bias[gcol], b1 = bias[gcol + 1];
#pragma unroll
                for (int rr = 0; rr < 2; rr++) {
                    int row = grow + rr * 8;
                    int t = row >> 1, b_ = row & 1;
                    size_t idx = (((size_t)(b_ * 16 + hh)) * SEQ + t) * 64 + dd;
                    float v0 = (acc[mt][nt][rr * 2]     + b0) * scl;
                    float v1 = (acc[mt][nt][rr * 2 + 1] + b1) * scl;
                    *(uint32_t*)(dhi + idx) = pack2h(v0, v1);
                }
            }
        }
    }
}

// ---------------------------------------------------------------------------
// Flash attention: single-MMA QK (q fp16), P in fp16 via ex2.approx.f16x2,
// row-sum l via hoisted ones-column MMA. CTA: 128 queries x one (b,h),
// 8 warps x 16 rows. 64-key tiles, 4-stage KV ring, CP_WAIT(2), one barrier
// per k-tile. Descending-qt launch order = LPT schedule.
// Output: single fp16 ctx [m][1024].
// ---------------------------------------------------------------------------
#define FQ 0
#define FKV_O 18432
#define FKV_STAGE 18432                // kh 0 | vh 9216
#define FSMEM_TOTAL (FKV_O + 4 * FKV_STAGE + 64)  // 92224

__global__ __launch_bounds__(256) void flash_mma(
    const __half* __restrict__ qh,
    const __half* __restrict__ kh, const __half* __restrict__ vh,
    __half* __restrict__ chi,
    int nqt)
{
    extern __shared__ char smem[];
    const uint32_t sb = smem_to_u32(smem);
    const int tid  = threadIdx.x;
    const int wid  = tid >> 5;
    const int lane = tid & 31;

    const int bx = blockIdx.x;
    const int bh_ = bx & 31;                // b*16 + h
    const int qt = nqt - 1 - (bx >> 5);     // big tiles first (LPT)
    const int b_ = bh_ >> 4;
    const int h  = bh_ & 15;
    const int t0 = qt * 128;
    const int nkt = 2 * (qt + 1);
    const size_t hb = ((size_t)(b_ * 16 + h)) * SEQ * 64;

#pragma unroll
    for (int c = tid; c < 1024; c += 256) {
        int r = c >> 3, ck = c & 7;
        cp_async16(sb + FQ + r * 144 + ck * 16, qh + hb + (size_t)(t0 + r) * 64 + ck * 8);
    }
    // ones-column init in V pad of STAGE 0 only (cols 64..71): col64=1, rest 0.
    for (int r = tid; r < 64; r += 256) {
        uint4 ones = {pack2h(1.f, 0.f), 0u, 0u, 0u};
        *(uint4*)(smem + FKV_O + 9216 + r * 144 + 128) = ones;
    }
    const __half* kvsrc[2] = {kh, vh};
    auto kv_stage = [&](int kt) -> uint32_t {
        return sb + FKV_O + (kt & 3) * FKV_STAGE;
    };
    auto load_kv = [&](int kt) {
        uint32_t st = kv_stage(kt);
        int kt0 = kt * 64;
#pragma unroll
        for (int c = tid; c < 1024; c += 256) {
            int tile = c >> 9, r = (c >> 3) & 63, ck = c & 7;
            cp_async16(st + tile * 9216 + r * 144 + ck * 16,
                       kvsrc[tile] + hb + (size_t)(kt0 + r) * 64 + ck * 8);
        }
    };
    // prologue: always 3 committed groups (empty beyond nkt)
    load_kv(0); CP_COMMIT();
    if (nkt > 1) load_kv(1);
    CP_COMMIT();
    if (nkt > 2) load_kv(2);
    CP_COMMIT();

    const int lrow = lane & 15;
    const int lcol = (lane >> 4) * 8;
    const int g    = lane >> 2;
    const int tig  = lane & 3;
    const int wq0  = wid * 16;
    const int row0 = t0 + wq0 + g;
    const int row1 = row0 + 8;
    const float L2E = 1.4426950408889634f;

    // hoisted ones fragment (stage 0 pad; needs only group 0 complete)
    CP_WAIT(2);
    __syncthreads();
    uint32_t bones[2];
    {
        uint32_t r0, r1, r2, r3;
        ldsm_x4_t(r0, r1, r2, r3, sb + FKV_O + 9216 + lrow * 144 + 128 + lcol * 2);
        bones[0] = r0; bones[1] = r1;
    }

    float o[8][4], osum[4];
#pragma unroll
    for (int nt = 0; nt < 8; nt++)
#pragma unroll
        for (int i = 0; i < 4; i++) o[nt][i] = 0.f;
#pragma unroll
    for (int i = 0; i < 4; i++) osum[i] = 0.f;
    float m0 = -1e30f, m1 = -1e30f;

    for (int kt = 0; kt < nkt; kt++) {
        CP_WAIT(2);
        __syncthreads();          // single barrier per k-tile
        if (kt + 3 < nkt) load_kv(kt + 3);
        CP_COMMIT();              // unconditional (possibly empty group)
        const int kt0 = kt * 64;
        const uint32_t st = kv_stage(kt);

        if (kt0 <= t0 + wq0 + 15) {
            // ---- S = Q @ K^T (single MMA, q fp16) ----
            float s[8][4];
#pragma unroll
            for (int nt = 0; nt < 8; nt++)
#pragma unroll
                for (int i = 0; i < 4; i++) s[nt][i] = 0.f;

#pragma unroll
            for (int ks = 0; ks < 4; ks++) {
                uint32_t ah[4];
                uint32_t qoff = (wq0 + lrow) * 144 + ks * 32 + lcol * 2;
                ldsm_x4(ah[0], ah[1], ah[2], ah[3], sb + FQ + qoff);
                uint32_t bkh[8][2];
#pragma unroll
                for (int np = 0; np < 4; np++) {
                    uint32_t koff = (np * 16 + lrow) * 144 + ks * 32 + lcol * 2;
                    uint32_t r0, r1, r2, r3;
                    ldsm_x4(r0, r1, r2, r3, st + koff);
                    bkh[np * 2][0] = r0; bkh[np * 2][1] = r2;
                    bkh[np * 2 + 1][0] = r1; bkh[np * 2 + 1][1] = r3;
                }
#pragma unroll
                for (int nt = 0; nt < 8; nt++)
                    mma_f16(s[nt], ah, bkh[nt]);
            }

            // ---- causal mask (diagonal band only) ----
            if (kt0 + 63 > t0 + wq0) {
#pragma unroll
                for (int nt = 0; nt < 8; nt++) {
                    int col = kt0 + nt * 8 + tig * 2;
                    if (col     > row0) s[nt][0] = -1e30f;
                    if (col + 1 > row0) s[nt][1] = -1e30f;
                    if (col     > row1) s[nt][2] = -1e30f;
                    if (col + 1 > row1) s[nt][3] = -1e30f;
                }
            }

            // ---- online softmax: max in fp32, exp in fp16x2 ----
            float mx0 = -1e30f, mx1 = -1e30f;
#pragma unroll
            for (int nt = 0; nt < 8; nt++) {
                mx0 = fmaxf(mx0, fmaxf(s[nt][0], s[nt][1]));
                mx1 = fmaxf(mx1, fmaxf(s[nt][2], s[nt][3]));
            }
#pragma unroll
            for (int off = 1; off < 4; off <<= 1) {
                mx0 = fmaxf(mx0, __shfl_xor_sync(0xFFFFFFFFu, mx0, off));
                mx1 = fmaxf(mx1, __shfl_xor_sync(0xFFFFFFFFu, mx1, off));
            }
            float nm0 = fmaxf(m0, mx0), nm1 = fmaxf(m1, mx1);
            float a0 = __expf(m0 - nm0), a1 = __expf(m1 - nm1);
            m0 = nm0; m1 = nm1;
            const float c0 = nm0 * L2E, c1 = nm1 * L2E;

            // P fragments straight from ex2.approx.f16x2
            uint32_t ph[4][4];
#pragma unroll
            for (int ks = 0; ks < 4; ks++) {
                ph[ks][0] = exp2h2(fmaf(s[2*ks][0],   L2E, -c0), fmaf(s[2*ks][1],   L2E, -c0));
                ph[ks][1] = exp2h2(fmaf(s[2*ks][2],   L2E, -c1), fmaf(s[2*ks][3],   L2E, -c1));
                ph[ks][2] = exp2h2(fmaf(s[2*ks+1][0], L2E, -c0), fmaf(s[2*ks+1][1], L2E, -c0));
                ph[ks][3] = exp2h2(fmaf(s[2*ks+1][2], L2E, -c1), fmaf(s[2*ks+1][3], L2E, -c1));
            }

            // rescale accumulators
#pragma unroll
            for (int nt = 0; nt < 8; nt++) {
                o[nt][0] *= a0; o[nt][1] *= a0;
                o[nt][2] *= a1; o[nt][3] *= a1;
            }
            osum[0] *= a0; osum[1] *= a0; osum[2] *= a1; osum[3] *= a1;

            // ---- O += P @ V ;  osum += P @ ones ----
#pragma unroll
            for (int ks = 0; ks < 4; ks++) {
                uint32_t bvh[8][2];
#pragma unroll
                for (int db = 0; db < 4; db++) {
                    uint32_t voff = (ks * 16 + lrow) * 144 + db * 32 + lcol * 2;
                    uint32_t r0, r1, r2, r3;
                    ldsm_x4_t(r0, r1, r2, r3, st + 9216 + voff);
                    bvh[db * 2][0] = r0; bvh[db * 2][1] = r1;
                    bvh[db * 2 + 1][0] = r2; bvh[db * 2 + 1][1] = r3;
                }
#pragma unroll
                for (int nt = 0; nt < 8; nt++) {
                    mma_f16(o[nt], ph[ks], bvh[nt]);
                }
                mma_f16(osum, ph[ks], bones);
            }
        }
    }

    // ---- epilogue: l from ones-column MMA (col 64 -> tig==0 lanes) ----
    float lz0 = __shfl_sync(0xFFFFFFFFu, osum[0], lane & 28);
    float lz1 = __shfl_sync(0xFFFFFFFFu, osum[2], lane & 28);
    const float i0 = 1.f / lz0;
    const float i1 = 1.f / lz1;
#pragma unroll
    for (int nt = 0; nt < 8; nt++) {
        const int d = nt * 8 + tig * 2;
        size_t o0 = ((size_t)(row0 * BATCH + b_)) * D_MODEL + h * 64 + d;
        size_t o1 = ((size_t)(row1 * BATCH + b_)) * D_MODEL + h * 64 + d;
        *(uint32_t*)(chi + o0) = pack2h(o[nt][0] * i0, o[nt][1] * i0);
        *(uint32_t*)(chi + o1) = pack2h(o[nt][2] * i1, o[nt][3] * i1);
    }
}

// ---------------------------------------------------------------------------
extern "C" void kernel_launch(void* const* d_in, const int* in_sizes, int n_in,
                              void* d_out, int out_size)
{
    const float* x    = (const float*)d_in[0];
    const float* Wqkv = (const float*)d_in[1];
    const float* bqkv = (const float*)d_in[2];
    const float* Wout = (const float*)d_in[3];
    const float* bout = (const float*)d_in[4];
    float* out = (float*)d_out;

    const int M = in_sizes[0] / D_MODEL;   // 4096
    const int T = M / BATCH;               // 2048
    const int nqt = T / 128;               // 16

    __half *xh, *w1h, *w2h, *chi, *qh, *kh, *vh;
    cudaGetSymbolAddress((void**)&xh, g_xh);
    cudaGetSymbolAddress((void**)&w1h, g_w1h);
    cudaGetSymbolAddress((void**)&w2h, g_w2h);
    cudaGetSymbolAddress((void**)&chi, g_chi);
    cudaGetSymbolAddress((void**)&qh, g_qh);
    cudaGetSymbolAddress((void**)&kh, g_kh);
    cudaGetSymbolAddress((void**)&vh, g_vh);

    cudaFuncSetAttribute(gemm_mma<1>, cudaFuncAttributeMaxDynamicSharedMemorySize, GSMEM_TOTAL);
    cudaFuncSetAttribute(gemm_mma<2>, cudaFuncAttributeMaxDynamicSharedMemorySize, GSMEM_TOTAL);
    cudaFuncSetAttribute(flash_mma, cudaFuncAttributeMaxDynamicSharedMemorySize, FSMEM_TOTAL);

    // 1) convert inputs to fp16
    convert_lin<<<(M * D_MODEL / 4 + 255) / 256, 256>>>(x, xh, M * D_MODEL / 4);
    convert_T<<<dim3(3 * D_MODEL / 32, D_MODEL / 32), dim3(32, 8)>>>(
        Wqkv, w1h, D_MODEL, 3 * D_MODEL);

    // 2) QKV projection (single-MMA) -> q/k/v fp16 [B,H,T,64]
    gemm_mma<1><<<dim3(3 * D_MODEL / 128, M / 128), 256, GSMEM_TOTAL>>>(
        xh, w1h, bqkv, nullptr, qh, kh, vh, M, 3 * D_MODEL, D_MODEL);

    // 3) causal flash attention -> single fp16 ctx
    flash_mma<<<32 * nqt, 256, FSMEM_TOTAL>>>(qh, kh, vh, chi, nqt);

    // 4) output projection (single-MMA)
    convert_T<<<dim3(D_MODEL / 32, D_MODEL / 32), dim3(32, 8)>>>(
        Wout, w2h, D_MODEL, D_MODEL);
    gemm_mma<2><<<dim3(D_MODEL / 128, M / 128), 256, GSMEM_TOTAL>>>(
        chi, w2h, bout, out, nullptr, nullptr, nullptr, M, D_MODEL, D_MODEL);
}

// round 17
// speedup vs baseline: 1.0650x; 1.0650x over previous
#include <cuda_runtime.h>
#include <cuda_fp16.h>
#include <cstdint>
#include <math.h>

#define D_MODEL 1024
#define N_HEADS 16
#define HEAD_DIM 64
#define BATCH 2
#define SEQ 2048

// ---------------------------------------------------------------------------
// Scratch (allocation-free rule: __device__ globals)
// ---------------------------------------------------------------------------
__device__ __half g_xh[4096 * 1024];         // x fp16
__device__ __half g_w1h[3072 * 1024];        // Wqkv^T fp16  [N,K]
__device__ __half g_w2h[1024 * 1024];        // Wout^T fp16  [N,K]
// q/k/v single fp16, [B,H,T,64] (q prescaled by 0.125)
__device__ __half g_qh[BATCH * N_HEADS * SEQ * 64];
__device__ __half g_kh[BATCH * N_HEADS * SEQ * 64];
__device__ __half g_vh[BATCH * N_HEADS * SEQ * 64];
// attention output (ctx) single fp16, [m=T*B rows][1024]
__device__ __half g_chi[4096 * 1024];

// ---------------------------------------------------------------------------
// PTX helpers (plain sm_103-compatible: mma.sync / ldmatrix / cp.async)
// ---------------------------------------------------------------------------
__device__ __forceinline__ uint32_t smem_to_u32(const void* p) {
    uint32_t a;
    asm("{ .reg .u64 t; cvta.to.shared.u64 t, %1; cvt.u32.u64 %0, t; }" : "=r"(a) : "l"(p));
    return a;
}
__device__ __forceinline__ void cp_async16(uint32_t dst, const void* src) {
    asm volatile("cp.async.cg.shared.global [%0], [%1], 16;" :: "r"(dst), "l"(src) : "memory");
}
#define CP_COMMIT() asm volatile("cp.async.commit_group;" ::: "memory")
#define CP_WAIT(n)  asm volatile("cp.async.wait_group %0;" :: "n"(n) : "memory")

__device__ __forceinline__ void ldsm_x4(uint32_t& r0, uint32_t& r1, uint32_t& r2, uint32_t& r3,
                                        uint32_t addr) {
    asm volatile("ldmatrix.sync.aligned.m8n8.x4.shared.b16 {%0,%1,%2,%3}, [%4];"
                 : "=r"(r0), "=r"(r1), "=r"(r2), "=r"(r3) : "r"(addr));
}
__device__ __forceinline__ void ldsm_x4_t(uint32_t& r0, uint32_t& r1, uint32_t& r2, uint32_t& r3,
                                          uint32_t addr) {
    asm volatile("ldmatrix.sync.aligned.m8n8.x4.trans.shared.b16 {%0,%1,%2,%3}, [%4];"
                 : "=r"(r0), "=r"(r1), "=r"(r2), "=r"(r3) : "r"(addr));
}
__device__ __forceinline__ void mma_f16(float c[4], const uint32_t a[4], const uint32_t b[2]) {
    asm volatile(
        "mma.sync.aligned.m16n8k16.row.col.f32.f16.f16.f32 "
        "{%0,%1,%2,%3}, {%4,%5,%6,%7}, {%8,%9}, {%0,%1,%2,%3};"
        : "+f"(c[0]), "+f"(c[1]), "+f"(c[2]), "+f"(c[3])
        : "r"(a[0]), "r"(a[1]), "r"(a[2]), "r"(a[3]), "r"(b[0]), "r"(b[1]));
}

__device__ __forceinline__ uint32_t pack2h(float x, float y) {
    __half2 h2 = __halves2half2(__float2half(x), __float2half(y));
    return *(uint32_t*)&h2;
}
// exp2 of a pair, result as packed fp16x2 (input pre-scaled by log2e)
__device__ __forceinline__ uint32_t exp2h2(float x, float y) {
    __half2 h = __floats2half2_rn(x, y);
    uint32_t r = *(uint32_t*)&h;
    uint32_t d;
    asm("ex2.approx.f16x2 %0, %1;" : "=r"(d) : "r"(r));
    return d;
}

// ---------------------------------------------------------------------------
// Conversion kernels
// ---------------------------------------------------------------------------
__global__ __launch_bounds__(256) void convert_lin(
    const float* __restrict__ in, __half* __restrict__ out, int n4)
{
    int i = blockIdx.x * blockDim.x + threadIdx.x;
    if (i >= n4) return;
    float4 v = ((const float4*)in)[i];
    ((__half2*)out)[i * 2]     = __floats2half2_rn(v.x, v.y);
    ((__half2*)out)[i * 2 + 1] = __floats2half2_rn(v.z, v.w);
}

// W[K,N] fp32 -> Wt [N,K] fp16 (transpose, round-to-nearest). 32x32 tiles.
__global__ __launch_bounds__(256) void convert_T(
    const float* __restrict__ W, __half* __restrict__ hi, int K, int N)
{
    __shared__ float t[32][33];
    const int n0 = blockIdx.x * 32;
    const int k0 = blockIdx.y * 32;
#pragma unroll
    for (int i = 0; i < 4; i++) {
        int k = k0 + threadIdx.y + i * 8;
        t[threadIdx.y + i * 8][threadIdx.x] = W[(size_t)k * N + n0 + threadIdx.x];
    }
    __syncthreads();
#pragma unroll
    for (int i = 0; i < 4; i++) {
        int nn = n0 + threadIdx.y + i * 8;
        hi[(size_t)nn * K + k0 + threadIdx.x] = __float2half(t[threadIdx.x][threadIdx.y + i * 8]);
    }
}

// ---------------------------------------------------------------------------
// fp16 GEMM (single MMA): C = Ah[M,K=1024] @ Bh[N,K]^T + bias
// CTA tile 128(M) x 128(N), BK=64, 256 threads (8 warps: 4M x 2N),
// warp tile 32x64. 3-stage cp.async ring, CP_WAIT(1), one barrier per kt
// (16 iterations), 2 CTAs/SM (221 KB total smem).
// MODE 1: QKV epilogue -> q/k/v fp16 [B,H,T,64] (q scaled by 0.125).
// MODE 2: fp32 C + bias.
// ---------------------------------------------------------------------------
#define BK 64
#define ASTRIDE 72                        // fp16 elems per smem row (64 + 8 pad)
#define TILE_BYTES (128 * ASTRIDE * 2)    // 18432
#define T_AH 0
#define T_BH  TILE_BYTES
#define STAGE_BYTES (2 * TILE_BYTES)      // 36864
#define GSMEM_TOTAL (3 * STAGE_BYTES)     // 110592

template <int MODE>
__global__ __launch_bounds__(256, 2) void gemm_mma(
    const __half* __restrict__ Ah, const __half* __restrict__ Bh,
    const float* __restrict__ bias, float* __restrict__ C,
    __half* __restrict__ qh, __half* __restrict__ kh, __half* __restrict__ vh,
    int M, int N, int K)
{
    extern __shared__ char smem[];
    const uint32_t smem_base = smem_to_u32(smem);
    const int tid  = threadIdx.x;
    const int wid  = tid >> 5;
    const int lane = tid & 31;
    const int bm = blockIdx.y * 128;
    const int bn = blockIdx.x * 128;
    const int wm = (wid & 3) * 32;
    const int wn = (wid >> 2) * 64;

    auto load_stage = [&](int it) {
        const uint32_t sb = smem_base + (it % 3) * STAGE_BYTES;
        const int k0 = it * BK;
#pragma unroll
        for (int c = tid; c < 2048; c += 256) {
            int kc = (c & 7) * 8;
            const __half* src;
            uint32_t dst;
            if (c < 1024) {            // A: 128 rows x 64 cols
                int r = c >> 3;
                src = Ah + (size_t)(bm + r) * K + k0 + kc;
                dst = sb + T_AH + (r * ASTRIDE + kc) * 2;
            } else {                   // B
                int r = (c - 1024) >> 3;
                src = Bh + (size_t)(bn + r) * K + k0 + kc;
                dst = sb + T_BH + (r * ASTRIDE + kc) * 2;
            }
            cp_async16(dst, src);
        }
    };

    const int NK = K / BK;             // 16
    load_stage(0); CP_COMMIT();
    load_stage(1); CP_COMMIT();

    float acc[2][8][4];
#pragma unroll
    for (int mt = 0; mt < 2; mt++)
#pragma unroll
        for (int nt = 0; nt < 8; nt++)
#pragma unroll
            for (int i = 0; i < 4; i++) acc[mt][nt][i] = 0.f;

    const int lrow = lane & 15;
    const int lcol = (lane >> 4) * 8;

    for (int kt = 0; kt < NK; kt++) {
        CP_WAIT(1);
        __syncthreads();       // single barrier per kt (3-stage ring)
        if (kt + 2 < NK) load_stage(kt + 2);
        CP_COMMIT();           // unconditional (possibly empty group)
        const uint32_t sb = smem_base + (kt % 3) * STAGE_BYTES;

#pragma unroll
        for (int ks = 0; ks < 4; ks++) {
            uint32_t ah[2][4];
#pragma unroll
            for (int mt = 0; mt < 2; mt++) {
                uint32_t off = ((wm + mt * 16 + lrow) * ASTRIDE + ks * 16 + lcol) * 2;
                ldsm_x4(ah[mt][0], ah[mt][1], ah[mt][2], ah[mt][3], sb + T_AH + off);
            }
            uint32_t bh[8][2];
#pragma unroll
            for (int np = 0; np < 4; np++) {
                uint32_t off = ((wn + np * 16 + lrow) * ASTRIDE + ks * 16 + lcol) * 2;
                uint32_t r0, r1, r2, r3;
                ldsm_x4(r0, r1, r2, r3, sb + T_BH + off);
                bh[np * 2][0] = r0; bh[np * 2][1] = r2;
                bh[np * 2 + 1][0] = r1; bh[np * 2 + 1][1] = r3;
            }
#pragma unroll
            for (int mt = 0; mt < 2; mt++)
#pragma unroll
                for (int nt = 0; nt < 8; nt++)
                    mma_f16(acc[mt][nt], ah[mt], bh[nt]);
        }
    }

    const int trow = lane >> 2;
    const int tcol = (lane & 3) * 2;

    if (MODE == 2) {
#pragma unroll
        for (int mt = 0; mt < 2; mt++) {
            const int grow = bm + wm + mt * 16 + trow;
#pragma unroll
            for (int nt = 0; nt < 8; nt++) {
                const int gcol = bn + wn + nt * 8 + tcol;
                float b0 = bias[gcol], b1 = bias[gcol + 1];
                float2 o0 = {acc[mt][nt][0] + b0, acc[mt][nt][1] + b1};
                float2 o1 = {acc[mt][nt][2] + b0, acc[mt][nt][3] + b1};
                *(float2*)(C + (size_t)grow * N + gcol)       = o0;
                *(float2*)(C + (size_t)(grow + 8) * N + gcol) = o1;
            }
        }
    } else {
        const int sec = bn >> 10;   // 0:q 1:k 2:v (uniform per CTA: 1024%128==0)
        __half* dhi = (sec == 0) ? qh : (sec == 1) ? kh : vh;
        const float scl = (sec == 0) ? 0.125f : 1.f;
#pragma unroll
        for (int mt = 0; mt < 2; mt++) {
            const int grow = bm + wm + mt * 16 + trow;
#pragma unroll
            for (int nt = 0; nt < 8; nt++) {
                const int gcol = bn + wn + nt * 8 + tcol;
                const int hh = (gcol >> 6) & 15;
                const int dd = gcol & 63;
                float b0 = bias[gcol], b1 = bias[gcol + 1];
#pragma unroll
                for (int rr = 0; rr < 2; rr++) {
                    int row = grow + rr * 8;
                    int t = row >> 1, b_ = row & 1;
                    size_t idx = (((size_t)(b_ * 16 + hh)) * SEQ + t) * 64 + dd;
                    float v0 = (acc[mt][nt][rr * 2]     + b0) * scl;
                    float v1 = (acc[mt][nt][rr * 2 + 1] + b1) * scl;
                    *(uint32_t*)(dhi + idx) = pack2h(v0, v1);
                }
            }
        }
    }
}

// ---------------------------------------------------------------------------
// Flash attention: single-MMA QK (q fp16), P in fp16 via ex2.approx.f16x2,
// row-sum l via hoisted ones-column MMA. CTA: 128 queries x one (b,h),
// 8 warps x 16 rows. 64-key tiles, 4-stage KV ring, CP_WAIT(2), one barrier
// per k-tile. Descending-qt launch order = LPT schedule.
// Output: single fp16 ctx [m][1024].
// ---------------------------------------------------------------------------
#define FQ 0
#define FKV_O 18432
#define FKV_STAGE 18432                // kh 0 | vh 9216
#define FSMEM_TOTAL (FKV_O + 4 * FKV_STAGE + 64)  // 92224

__global__ __launch_bounds__(256) void flash_mma(
    const __half* __restrict__ qh,
    const __half* __restrict__ kh, const __half* __restrict__ vh,
    __half* __restrict__ chi,
    int nqt)
{
    extern __shared__ char smem[];
    const uint32_t sb = smem_to_u32(smem);
    const int tid  = threadIdx.x;
    const int wid  = tid >> 5;
    const int lane = tid & 31;

    const int bx = blockIdx.x;
    const int bh_ = bx & 31;                // b*16 + h
    const int qt = nqt - 1 - (bx >> 5);     // big tiles first (LPT)
    const int b_ = bh_ >> 4;
    const int h  = bh_ & 15;
    const int t0 = qt * 128;
    const int nkt = 2 * (qt + 1);
    const size_t hb = ((size_t)(b_ * 16 + h)) * SEQ * 64;

#pragma unroll
    for (int c = tid; c < 1024; c += 256) {
        int r = c >> 3, ck = c & 7;
        cp_async16(sb + FQ + r * 144 + ck * 16, qh + hb + (size_t)(t0 + r) * 64 + ck * 8);
    }
    // ones-column init in V pad of STAGE 0 only (cols 64..71): col64=1, rest 0.
    for (int r = tid; r < 64; r += 256) {
        uint4 ones = {pack2h(1.f, 0.f), 0u, 0u, 0u};
        *(uint4*)(smem + FKV_O + 9216 + r * 144 + 128) = ones;
    }
    const __half* kvsrc[2] = {kh, vh};
    auto kv_stage = [&](int kt) -> uint32_t {
        return sb + FKV_O + (kt & 3) * FKV_STAGE;
    };
    auto load_kv = [&](int kt) {
        uint32_t st = kv_stage(kt);
        int kt0 = kt * 64;
#pragma unroll
        for (int c = tid; c < 1024; c += 256) {
            int tile = c >> 9, r = (c >> 3) & 63, ck = c & 7;
            cp_async16(st + tile * 9216 + r * 144 + ck * 16,
                       kvsrc[tile] + hb + (size_t)(kt0 + r) * 64 + ck * 8);
        }
    };
    // prologue: always 3 committed groups (empty beyond nkt)
    load_kv(0); CP_COMMIT();
    if (nkt > 1) load_kv(1);
    CP_COMMIT();
    if (nkt > 2) load_kv(2);
    CP_COMMIT();

    const int lrow = lane & 15;
    const int lcol = (lane >> 4) * 8;
    const int g    = lane >> 2;
    const int tig  = lane & 3;
    const int wq0  = wid * 16;
    const int row0 = t0 + wq0 + g;
    const int row1 = row0 + 8;
    const float L2E = 1.4426950408889634f;

    // hoisted ones fragment (stage 0 pad; needs only group 0 complete)
    CP_WAIT(2);
    __syncthreads();
    uint32_t bones[2];
    {
        uint32_t r0, r1, r2, r3;
        ldsm_x4_t(r0, r1, r2, r3, sb + FKV_O + 9216 + lrow * 144 + 128 + lcol * 2);
        bones[0] = r0; bones[1] = r1;
    }

    float o[8][4], osum[4];
#pragma unroll
    for (int nt = 0; nt < 8; nt++)
#pragma unroll
        for (int i = 0; i < 4; i++) o[nt][i] = 0.f;
#pragma unroll
    for (int i = 0; i < 4; i++) osum[i] = 0.f;
    float m0 = -1e30f, m1 = -1e30f;

    for (int kt = 0; kt < nkt; kt++) {
        CP_WAIT(2);
        __syncthreads();          // single barrier per k-tile
        if (kt + 3 < nkt) load_kv(kt + 3);
        CP_COMMIT();              // unconditional (possibly empty group)
        const int kt0 = kt * 64;
        const uint32_t st = kv_stage(kt);

        if (kt0 <= t0 + wq0 + 15) {
            // ---- S = Q @ K^T (single MMA, q fp16) ----
            float s[8][4];
#pragma unroll
            for (int nt = 0; nt < 8; nt++)
#pragma unroll
                for (int i = 0; i < 4; i++) s[nt][i] = 0.f;

#pragma unroll
            for (int ks = 0; ks < 4; ks++) {
                uint32_t ah[4];
                uint32_t qoff = (wq0 + lrow) * 144 + ks * 32 + lcol * 2;
                ldsm_x4(ah[0], ah[1], ah[2], ah[3], sb + FQ + qoff);
                uint32_t bkh[8][2];
#pragma unroll
                for (int np = 0; np < 4; np++) {
                    uint32_t koff = (np * 16 + lrow) * 144 + ks * 32 + lcol * 2;
                    uint32_t r0, r1, r2, r3;
                    ldsm_x4(r0, r1, r2, r3, st + koff);
                    bkh[np * 2][0] = r0; bkh[np * 2][1] = r2;
                    bkh[np * 2 + 1][0] = r1; bkh[np * 2 + 1][1] = r3;
                }
#pragma unroll
                for (int nt = 0; nt < 8; nt++)
                    mma_f16(s[nt], ah, bkh[nt]);
            }

            // ---- causal mask (diagonal band only) ----
            if (kt0 + 63 > t0 + wq0) {
#pragma unroll
                for (int nt = 0; nt < 8; nt++) {
                    int col = kt0 + nt * 8 + tig * 2;
                    if (col     > row0) s[nt][0] = -1e30f;
                    if (col + 1 > row0) s[nt][1] = -1e30f;
                    if (col     > row1) s[nt][2] = -1e30f;
                    if (col + 1 > row1) s[nt][3] = -1e30f;
                }
            }

            // ---- online softmax: max in fp32, exp in fp16x2 ----
            float mx0 = -1e30f, mx1 = -1e30f;
#pragma unroll
            for (int nt = 0; nt < 8; nt++) {
                mx0 = fmaxf(mx0, fmaxf(s[nt][0], s[nt][1]));
                mx1 = fmaxf(mx1, fmaxf(s[nt][2], s[nt][3]));
            }
#pragma unroll
            for (int off = 1; off < 4; off <<= 1) {
                mx0 = fmaxf(mx0, __shfl_xor_sync(0xFFFFFFFFu, mx0, off));
                mx1 = fmaxf(mx1, __shfl_xor_sync(0xFFFFFFFFu, mx1, off));
            }
            float nm0 = fmaxf(m0, mx0), nm1 = fmaxf(m1, mx1);
            float a0 = __expf(m0 - nm0), a1 = __expf(m1 - nm1);
            m0 = nm0; m1 = nm1;
            const float c0 = nm0 * L2E, c1 = nm1 * L2E;

            // P fragments straight from ex2.approx.f16x2
            uint32_t ph[4][4];
#pragma unroll
            for (int ks = 0; ks < 4; ks++) {
                ph[ks][0] = exp2h2(fmaf(s[2*ks][0],   L2E, -c0), fmaf(s[2*ks][1],   L2E, -c0));
                ph[ks][1] = exp2h2(fmaf(s[2*ks][2],   L2E, -c1), fmaf(s[2*ks][3],   L2E, -c1));
                ph[ks][2] = exp2h2(fmaf(s[2*ks+1][0], L2E, -c0), fmaf(s[2*ks+1][1], L2E, -c0));
                ph[ks][3] = exp2h2(fmaf(s[2*ks+1][2], L2E, -c1), fmaf(s[2*ks+1][3], L2E, -c1));
            }

            // rescale accumulators
#pragma unroll
            for (int nt = 0; nt < 8; nt++) {
                o[nt][0] *= a0; o[nt][1] *= a0;
                o[nt][2] *= a1; o[nt][3] *= a1;
            }
            osum[0] *= a0; osum[1] *= a0; osum[2] *= a1; osum[3] *= a1;

            // ---- O += P @ V ;  osum += P @ ones ----
#pragma unroll
            for (int ks = 0; ks < 4; ks++) {
                uint32_t bvh[8][2];
#pragma unroll
                for (int db = 0; db < 4; db++) {
                    uint32_t voff = (ks * 16 + lrow) * 144 + db * 32 + lcol * 2;
                    uint32_t r0, r1, r2, r3;
                    ldsm_x4_t(r0, r1, r2, r3, st + 9216 + voff);
                    bvh[db * 2][0] = r0; bvh[db * 2][1] = r1;
                    bvh[db * 2 + 1][0] = r2; bvh[db * 2 + 1][1] = r3;
                }
#pragma unroll
                for (int nt = 0; nt < 8; nt++) {
                    mma_f16(o[nt], ph[ks], bvh[nt]);
                }
                mma_f16(osum, ph[ks], bones);
            }
        }
    }

    // ---- epilogue: l from ones-column MMA (col 64 -> tig==0 lanes) ----
    float lz0 = __shfl_sync(0xFFFFFFFFu, osum[0], lane & 28);
    float lz1 = __shfl_sync(0xFFFFFFFFu, osum[2], lane & 28);
    const float i0 = 1.f / lz0;
    const float i1 = 1.f / lz1;
#pragma unroll
    for (int nt = 0; nt < 8; nt++) {
        const int d = nt * 8 + tig * 2;
        size_t o0 = ((size_t)(row0 * BATCH + b_)) * D_MODEL + h * 64 + d;
        size_t o1 = ((size_t)(row1 * BATCH + b_)) * D_MODEL + h * 64 + d;
        *(uint32_t*)(chi + o0) = pack2h(o[nt][0] * i0, o[nt][1] * i0);
        *(uint32_t*)(chi + o1) = pack2h(o[nt][2] * i1, o[nt][3] * i1);
    }
}

// ---------------------------------------------------------------------------
extern "C" void kernel_launch(void* const* d_in, const int* in_sizes, int n_in,
                              void* d_out, int out_size)
{
    const float* x    = (const float*)d_in[0];
    const float* Wqkv = (const float*)d_in[1];
    const float* bqkv = (const float*)d_in[2];
    const float* Wout = (const float*)d_in[3];
    const float* bout = (const float*)d_in[4];
    float* out = (float*)d_out;

    const int M = in_sizes[0] / D_MODEL;   // 4096
    const int T = M / BATCH;               // 2048
    const int nqt = T / 128;               // 16

    __half *xh, *w1h, *w2h, *chi, *qh, *kh, *vh;
    cudaGetSymbolAddress((void**)&xh, g_xh);
    cudaGetSymbolAddress((void**)&w1h, g_w1h);
    cudaGetSymbolAddress((void**)&w2h, g_w2h);
    cudaGetSymbolAddress((void**)&chi, g_chi);
    cudaGetSymbolAddress((void**)&qh, g_qh);
    cudaGetSymbolAddress((void**)&kh, g_kh);
    cudaGetSymbolAddress((void**)&vh, g_vh);

    cudaFuncSetAttribute(gemm_mma<1>, cudaFuncAttributeMaxDynamicSharedMemorySize, GSMEM_TOTAL);
    cudaFuncSetAttribute(gemm_mma<2>, cudaFuncAttributeMaxDynamicSharedMemorySize, GSMEM_TOTAL);
    cudaFuncSetAttribute(flash_mma, cudaFuncAttributeMaxDynamicSharedMemorySize, FSMEM_TOTAL);

    // 1) convert inputs to fp16
    convert_lin<<<(M * D_MODEL / 4 + 255) / 256, 256>>>(x, xh, M * D_MODEL / 4);
    convert_T<<<dim3(3 * D_MODEL / 32, D_MODEL / 32), dim3(32, 8)>>>(
        Wqkv, w1h, D_MODEL, 3 * D_MODEL);

    // 2) QKV projection (single-MMA) -> q/k/v fp16 [B,H,T,64]
    gemm_mma<1><<<dim3(3 * D_MODEL / 128, M / 128), 256, GSMEM_TOTAL>>>(
        xh, w1h, bqkv, nullptr, qh, kh, vh, M, 3 * D_MODEL, D_MODEL);

    // 3) causal flash attention -> single fp16 ctx
    flash_mma<<<32 * nqt, 256, FSMEM_TOTAL>>>(qh, kh, vh, chi, nqt);

    // 4) output projection (single-MMA)
    convert_T<<<dim3(D_MODEL / 32, D_MODEL / 32), dim3(32, 8)>>>(
        Wout, w2h, D_MODEL, D_MODEL);
    gemm_mma<2><<<dim3(D_MODEL / 128, M / 128), 256, GSMEM_TOTAL>>>(
        chi, w2h, bout, out, nullptr, nullptr, nullptr, M, D_MODEL, D_MODEL);
}